// round 1
// baseline (speedup 1.0000x reference)
#include <cuda_runtime.h>

#define IMG 96
#define CH 96
#define NB 16
#define CK 16
#define CO_TILE 32
#define SPR 8
#define SPC 16

// Scratch (allocation-free): ~170 MB of __device__ globals.
__device__ float g_u1[(size_t)NB*CH*9*1024];     // unfolded conv1 output
__device__ float g_u2[(size_t)NB*CH*9*1024];     // unfolded conv2 output
__device__ float g_y3[(size_t)NB*CH*IMG*IMG];    // conv3 output (NCHW)
__device__ float g_S [(size_t)NB*CH*CH*9];       // attn logits -> softmax weights

// ---------------------------------------------------------------------------
// Direct 3x3 same-padding conv, 96ch -> 96ch, fp32.
// Block: 256 threads. Tile: 32 couts x (8x16) spatial. Thread: 4 couts x 4 cols.
// UNFOLD_OUT: write output in nn.Unfold(3, stride=3) layout [b][c][k][l].
// PBW: weights are per-batch (stage-4 attention conv).
// ---------------------------------------------------------------------------
template<int UNFOLD_OUT, int PBW>
__global__ __launch_bounds__(256)
void conv3x3_kernel(const float* __restrict__ x, const float* __restrict__ wgl,
                    float* __restrict__ out)
{
    __shared__ float sIn[CK][SPR+2][19];        // 18 valid cols, stride 19 (odd)
    __shared__ float sW [CK][9][CO_TILE+1];     // stride 33 (odd) -> conflict-free fill

    const int b      = blockIdx.z;
    const int coBase = blockIdx.y * CO_TILE;
    const int rowTile = blockIdx.x / (IMG/SPC);
    const int colTile = blockIdx.x % (IMG/SPC);
    const int th = rowTile * SPR;
    const int tw = colTile * SPC;
    const int tid = threadIdx.x;
    const int co_t = tid >> 5;                  // 0..7 (4 couts each)
    const int sp   = tid & 31;                  // 32 spatial groups
    const int rr   = sp >> 2;                   // row within tile 0..7
    const int cc   = (sp & 3) << 2;             // col base within tile {0,4,8,12}

    const float* wb = wgl + (PBW ? (size_t)b*CH*CH*9 : (size_t)0);
    const float* xb = x + (size_t)b*CH*IMG*IMG;

    float acc[4][4];
    #pragma unroll
    for (int a = 0; a < 4; a++)
        #pragma unroll
        for (int j = 0; j < 4; j++) acc[a][j] = 0.f;

    for (int c0 = 0; c0 < CH; c0 += CK) {
        // --- load input halo tile: CK x 10 x 18 (zero-padded borders) ---
        for (int e = tid; e < CK*(SPR+2)*(SPC+2); e += 256) {
            int ci  = e / ((SPR+2)*(SPC+2));
            int rem = e - ci*((SPR+2)*(SPC+2));
            int r   = rem / (SPC+2);
            int c   = rem - r*(SPC+2);
            int gh = th + r - 1, gw = tw + c - 1;
            float v = 0.f;
            if ((unsigned)gh < IMG && (unsigned)gw < IMG)
                v = xb[((size_t)(c0+ci)*IMG + gh)*IMG + gw];
            sIn[ci][r][c] = v;
        }
        // --- load weights: sW[ci][tap][co], coalesced over (ci,tap) per co ---
        for (int e = tid; e < CK*9*CO_TILE; e += 256) {
            int co  = e / (CK*9);
            int rem = e - co*(CK*9);
            int ci  = rem / 9;
            int tap = rem - ci*9;
            sW[ci][tap][co] = wb[((size_t)(coBase+co)*CH + c0 + ci)*9 + tap];
        }
        __syncthreads();

        #pragma unroll 4
        for (int ci = 0; ci < CK; ci++) {
            #pragma unroll
            for (int kh = 0; kh < 3; kh++) {
                float iv[6];
                #pragma unroll
                for (int j = 0; j < 6; j++) iv[j] = sIn[ci][rr+kh][cc+j];
                #pragma unroll
                for (int kw = 0; kw < 3; kw++) {
                    float w0 = sW[ci][kh*3+kw][co_t*4+0];
                    float w1 = sW[ci][kh*3+kw][co_t*4+1];
                    float w2 = sW[ci][kh*3+kw][co_t*4+2];
                    float w3 = sW[ci][kh*3+kw][co_t*4+3];
                    #pragma unroll
                    for (int j = 0; j < 4; j++) {
                        float xv = iv[kw+j];
                        acc[0][j] += w0*xv;
                        acc[1][j] += w1*xv;
                        acc[2][j] += w2*xv;
                        acc[3][j] += w3*xv;
                    }
                }
            }
        }
        __syncthreads();
    }

    const int h = th + rr;
    #pragma unroll
    for (int a = 0; a < 4; a++) {
        int co = coBase + co_t*4 + a;
        #pragma unroll
        for (int j = 0; j < 4; j++) {
            int wc = tw + cc + j;
            if (UNFOLD_OUT) {
                int k = (h % 3) * 3 + (wc % 3);
                int l = (h / 3) * 32 + (wc / 3);
                out[(((size_t)b*CH + co)*9 + k)*1024 + l] = acc[a][j];
            } else {
                out[(((size_t)b*CH + co)*IMG + h)*IMG + wc] = acc[a][j];
            }
        }
    }
}

// ---------------------------------------------------------------------------
// attn[b,k,c,d] = sum_l u1[b,c,k,l] * u2[b,d,k,l]   (144 GEMMs: 96x96, K=1024)
// Writes directly into softmax layout S[b][d][c][k].
// ---------------------------------------------------------------------------
__global__ __launch_bounds__(256)
void attn_gemm_kernel(const float* __restrict__ u1, const float* __restrict__ u2,
                      float* __restrict__ S)
{
    __shared__ float sA[16][97];
    __shared__ float sB[16][97];

    const int bk = blockIdx.x;
    const int b = bk / 9;
    const int k = bk - 9*b;
    const float* A  = u1 + ((size_t)b*CH*9 + k)*1024;   // row c, stride 9216
    const float* Bm = u2 + ((size_t)b*CH*9 + k)*1024;   // row d, stride 9216
    const int tid = threadIdx.x;
    const int tx = tid & 15, ty = tid >> 4;

    float acc[6][6] = {};

    const int kk = tid & 15;
    const int cb = tid >> 4;
    for (int l0 = 0; l0 < 1024; l0 += 16) {
        #pragma unroll
        for (int it = 0; it < 6; it++) {
            int c = cb + it*16;
            sA[kk][c] = A [(size_t)c*9216 + l0 + kk];
            sB[kk][c] = Bm[(size_t)c*9216 + l0 + kk];
        }
        __syncthreads();
        #pragma unroll
        for (int q = 0; q < 16; q++) {
            float av[6], bv[6];
            #pragma unroll
            for (int i = 0; i < 6; i++) av[i] = sA[q][ty*6+i];
            #pragma unroll
            for (int j = 0; j < 6; j++) bv[j] = sB[q][tx*6+j];
            #pragma unroll
            for (int i = 0; i < 6; i++)
                #pragma unroll
                for (int j = 0; j < 6; j++)
                    acc[i][j] += av[i]*bv[j];
        }
        __syncthreads();
    }

    #pragma unroll
    for (int i = 0; i < 6; i++) {
        int c = ty*6 + i;
        #pragma unroll
        for (int j = 0; j < 6; j++) {
            int d = tx*6 + j;
            S[(((size_t)b*CH + d)*CH + c)*9 + k] = acc[i][j];
        }
    }
}

// ---------------------------------------------------------------------------
// Row softmax over 864 contiguous elements (scale 1/sqrt(864)), in place.
// One block per (b,d) row; 1536 blocks.
// ---------------------------------------------------------------------------
__global__ __launch_bounds__(256)
void softmax_kernel(float* __restrict__ S)
{
    float* row = S + (size_t)blockIdx.x * 864;
    const int tid = threadIdx.x;
    const float scale = 1.0f / 29.393876913398138f;   // 1/sqrt(864)

    float vals[4];
    int cnt = 0;
    float m = -1e30f;
    for (int i = tid; i < 864; i += 256) {
        float v = row[i] * scale;
        vals[cnt++] = v;
        m = fmaxf(m, v);
    }

    __shared__ float redm[8];
    __shared__ float reds[8];
    #pragma unroll
    for (int o = 16; o; o >>= 1) m = fmaxf(m, __shfl_xor_sync(0xffffffffu, m, o));
    if ((tid & 31) == 0) redm[tid >> 5] = m;
    __syncthreads();
    float bm = redm[0];
    #pragma unroll
    for (int w = 1; w < 8; w++) bm = fmaxf(bm, redm[w]);

    float s = 0.f;
    for (int c = 0; c < cnt; c++) { vals[c] = expf(vals[c] - bm); s += vals[c]; }
    #pragma unroll
    for (int o = 16; o; o >>= 1) s += __shfl_xor_sync(0xffffffffu, s, o);
    if ((tid & 31) == 0) reds[tid >> 5] = s;
    __syncthreads();
    float bs = 0.f;
    #pragma unroll
    for (int w = 0; w < 8; w++) bs += reds[w];
    float inv = 1.0f / bs;

    cnt = 0;
    for (int i = tid; i < 864; i += 256) row[i] = vals[cnt++] * inv;
}

// ---------------------------------------------------------------------------
extern "C" void kernel_launch(void* const* d_in, const int* in_sizes, int n_in,
                              void* d_out, int out_size)
{
    const float* x  = (const float*)d_in[0];
    const float* W1 = (const float*)d_in[1];
    const float* W2 = (const float*)d_in[2];
    const float* W3 = (const float*)d_in[3];
    float* out = (float*)d_out;

    float *u1, *u2, *y3, *S;
    cudaGetSymbolAddress((void**)&u1, g_u1);
    cudaGetSymbolAddress((void**)&u2, g_u2);
    cudaGetSymbolAddress((void**)&y3, g_y3);
    cudaGetSymbolAddress((void**)&S,  g_S);

    dim3 cg((IMG/SPR)*(IMG/SPC), CH/CO_TILE, NB);   // (72, 3, 16)
    conv3x3_kernel<1,0><<<cg, 256>>>(x, W1, u1);    // conv1 -> unfold layout
    conv3x3_kernel<1,0><<<cg, 256>>>(x, W2, u2);    // conv2 -> unfold layout
    conv3x3_kernel<0,0><<<cg, 256>>>(x, W3, y3);    // conv3 -> NCHW
    attn_gemm_kernel<<<NB*9, 256>>>(u1, u2, S);     // 144 batched GEMMs
    softmax_kernel<<<NB*CH, 256>>>(S);              // 1536 rows of 864
    conv3x3_kernel<0,1><<<cg, 256>>>(y3, S, out);   // attention as per-batch conv
}

// round 6
// speedup vs baseline: 1.7194x; 1.7194x over previous
#include <cuda_runtime.h>
#include <cuda_bf16.h>
#include <cstdint>

#define IMG 96
#define CH 96
#define NB 16
#define NPIX (IMG*IMG)           // 9216
#define KREAL 864                // 96*9
#define KPAD 896                 // 14 * 64
#define KC 64                    // K-chunk (128B bf16 row)
#define NCHUNK (KPAD/KC)         // 14
#define NTILE 128                // pixels per GEMM tile
#define TILES_PER_B (NPIX/NTILE) // 72

// ---------------- device scratch (static, allocation-free; BSS => zeroed) ---
__device__ __align__(128) __nv_bfloat16 g_Bhi[(size_t)NB*NPIX*KPAD];  // im2col input hi (Xs, later Ys)
__device__ __align__(128) __nv_bfloat16 g_Blo[(size_t)NB*NPIX*KPAD];  // im2col input lo
__device__ __align__(128) __nv_bfloat16 g_W12h[(size_t)2*128*KPAD];
__device__ __align__(128) __nv_bfloat16 g_W12l[(size_t)2*128*KPAD];
__device__ __align__(128) __nv_bfloat16 g_W3h[(size_t)128*KPAD];
__device__ __align__(128) __nv_bfloat16 g_W3l[(size_t)128*KPAD];
__device__ __align__(128) __nv_bfloat16 g_Sh[(size_t)NB*128*KPAD];    // softmaxed attn hi
__device__ __align__(128) __nv_bfloat16 g_Sl[(size_t)NB*128*KPAD];
__device__ float g_u1[(size_t)NB*CH*9*1024];   // unfolded conv1 out
__device__ float g_u2[(size_t)NB*CH*9*1024];   // unfolded conv2 out
__device__ float g_y3[(size_t)NB*CH*NPIX];     // conv3 out NCHW
__device__ float g_S [(size_t)NB*CH*KREAL];    // attn logits (fp32)

// ---------------- helpers ----------------
__device__ __forceinline__ uint32_t smem_u32(const void* p) {
    uint32_t a;
    asm("{ .reg .u64 t; cvta.to.shared.u64 t, %1; cvt.u32.u64 %0, t; }" : "=r"(a) : "l"(p));
    return a;
}
__device__ __forceinline__ void cp_async16(uint32_t dst, const void* src) {
    asm volatile("cp.async.cg.shared.global [%0], [%1], 16;" :: "r"(dst), "l"(src));
}
__device__ __forceinline__ void cp_commit() { asm volatile("cp.async.commit_group;" ::: "memory"); }
template<int N>
__device__ __forceinline__ void cp_wait() { asm volatile("cp.async.wait_group %0;" :: "n"(N) : "memory"); }

__device__ __forceinline__ void ldsm_x4(uint32_t* r, uint32_t addr) {
    asm volatile("ldmatrix.sync.aligned.m8n8.x4.shared.b16 {%0,%1,%2,%3}, [%4];"
                 : "=r"(r[0]), "=r"(r[1]), "=r"(r[2]), "=r"(r[3]) : "r"(addr));
}
__device__ __forceinline__ void ldsm_x2(uint32_t* r, uint32_t addr) {
    asm volatile("ldmatrix.sync.aligned.m8n8.x2.shared.b16 {%0,%1}, [%2];"
                 : "=r"(r[0]), "=r"(r[1]) : "r"(addr));
}
__device__ __forceinline__ void mma_bf16(float* d, const uint32_t* a, const uint32_t* b) {
    asm volatile("mma.sync.aligned.m16n8k16.row.col.f32.bf16.bf16.f32 "
                 "{%0,%1,%2,%3}, {%4,%5,%6,%7}, {%8,%9}, {%0,%1,%2,%3};"
                 : "+f"(d[0]), "+f"(d[1]), "+f"(d[2]), "+f"(d[3])
                 : "r"(a[0]), "r"(a[1]), "r"(a[2]), "r"(a[3]), "r"(b[0]), "r"(b[1]));
}

// ---------------------------------------------------------------------------
// prep_shift: src NCHW fp32 -> dst[b][p][k] bf16 hi/lo, k = ci*9 + (dh*3+dw)
// ---------------------------------------------------------------------------
__global__ __launch_bounds__(256)
void prep_shift_kernel(const float* __restrict__ src,
                       __nv_bfloat16* __restrict__ dhi, __nv_bfloat16* __restrict__ dlo)
{
    __shared__ float sx[32][3][IMG];
    const int h   = blockIdx.x;
    const int ci0 = blockIdx.y * 32;
    const int b   = blockIdx.z;
    const int tid = threadIdx.x;

    for (int e = tid; e < 32*3*IMG; e += 256) {
        int ci = e / (3*IMG);
        int r  = (e / IMG) % 3;
        int w  = e % IMG;
        int gh = h + r - 1;
        float v = 0.f;
        if ((unsigned)gh < IMG)
            v = src[(((size_t)b*CH + ci0 + ci)*IMG + gh)*IMG + w];
        sx[ci][r][w] = v;
    }
    __syncthreads();

    const size_t rowbase = ((size_t)b*NPIX + (size_t)h*IMG) * KPAD + (size_t)ci0*9;
    for (int idx = tid; idx < IMG*288; idx += 256) {
        int w  = idx / 288;
        int kk = idx - w*288;
        int ci = kk / 9, tap = kk - ci*9;
        int dh = tap / 3, dw = tap - dh*3;
        int ww = w + dw - 1;
        float v = ((unsigned)ww < IMG) ? sx[ci][dh][ww] : 0.f;
        __nv_bfloat16 hi = __float2bfloat16(v);
        __nv_bfloat16 lo = __float2bfloat16(v - __bfloat162float(hi));
        size_t off = rowbase + (size_t)w*KPAD + kk;
        dhi[off] = hi; dlo[off] = lo;
    }
}

// ---------------------------------------------------------------------------
__global__ __launch_bounds__(256)
void prep_w_kernel(const float* __restrict__ W1, const float* __restrict__ W2,
                   const float* __restrict__ W3)
{
    int idx = blockIdx.x*256 + threadIdx.x;
    if (idx >= 3*CH*KREAL) return;
    int conv = idx / (CH*KREAL);
    int rem  = idx - conv*(CH*KREAL);
    int co = rem / KREAL, k = rem - co*KREAL;
    const float* W = (conv == 0) ? W1 : (conv == 1) ? W2 : W3;
    float v = W[(size_t)co*KREAL + k];
    __nv_bfloat16 hi = __float2bfloat16(v);
    __nv_bfloat16 lo = __float2bfloat16(v - __bfloat162float(hi));
    size_t off = (size_t)co*KPAD + k;
    if (conv < 2) { g_W12h[(size_t)conv*128*KPAD + off] = hi; g_W12l[(size_t)conv*128*KPAD + off] = lo; }
    else          { g_W3h[off] = hi; g_W3l[off] = lo; }
}

// ---------------------------------------------------------------------------
// gemm_conv: D[co][p] = sum_k A[co][k]*B[p][k] via mma.sync bf16 hi/lo (3-term).
// Block 256 thr (8 warps, 2x4), block tile M=96 x N=128, K=896 in 14x64 chunks.
// Each warp: 48x32 per conv (3 m16 x 4 n8 tiles). NCONV=2: both convs share B.
// smem/stage: [Bh,Bl,A0h,A0l(,A1h,A1l)] tiles of 128 rows x 128B, XOR-swizzled.
// ---------------------------------------------------------------------------
template<int NCONV, int EPI>
__global__ __launch_bounds__(256, 1)
void gemm_conv_kernel(const __nv_bfloat16* __restrict__ Bhi, const __nv_bfloat16* __restrict__ Blo,
                      const __nv_bfloat16* __restrict__ A0h, const __nv_bfloat16* __restrict__ A0l,
                      const __nv_bfloat16* __restrict__ A1h, const __nv_bfloat16* __restrict__ A1l,
                      long aStride, float* __restrict__ out0, float* __restrict__ out1)
{
    extern __shared__ __align__(1024) char smem[];
    constexpr int NT = 2 + 2*NCONV;
    constexpr int STAGE = NT * 16384;

    const int tid  = threadIdx.x;
    const int wid  = tid >> 5;
    const int lane = tid & 31;
    const int wm   = wid & 1;          // 2 warps over M
    const int wn   = wid >> 1;         // 4 warps over N
    const int ntile = blockIdx.x;
    const int b     = blockIdx.y;

    const uint32_t sb = smem_u32(smem);

    const __nv_bfloat16* srcs[6];
    srcs[0] = Bhi + ((size_t)b*NPIX + (size_t)ntile*NTILE)*KPAD;
    srcs[1] = Blo + ((size_t)b*NPIX + (size_t)ntile*NTILE)*KPAD;
    srcs[2] = A0h + (size_t)b*aStride;
    srcs[3] = A0l + (size_t)b*aStride;
    srcs[4] = (NCONV == 2) ? A1h + (size_t)b*aStride : srcs[2];
    srcs[5] = (NCONV == 2) ? A1l + (size_t)b*aStride : srcs[3];

    float acc[NCONV][3][4][4];
    #pragma unroll
    for (int cv = 0; cv < NCONV; cv++)
        #pragma unroll
        for (int mt = 0; mt < 3; mt++)
            #pragma unroll
            for (int nt = 0; nt < 4; nt++)
                #pragma unroll
                for (int j = 0; j < 4; j++) acc[cv][mt][nt][j] = 0.f;

    auto load_chunk = [&](int chunk, int stage) {
        uint32_t base = sb + stage*STAGE;
        #pragma unroll
        for (int t = 0; t < NT; t++) {
            const int rows = (t < 2) ? 128 : 96;
            const __nv_bfloat16* sp = srcs[t];
            #pragma unroll
            for (int e = tid; e < rows*8; e += 256) {
                int row = e >> 3, col = e & 7;
                uint32_t dst = base + t*16384 + row*128 + (((col ^ row) & 7) << 4);
                cp_async16(dst, sp + (size_t)row*KPAD + chunk*KC + col*8);
            }
        }
        cp_commit();
    };

    load_chunk(0, 0);

    for (int c = 0; c < NCHUNK; c++) {
        if (c + 1 < NCHUNK) { load_chunk(c+1, (c+1)&1); cp_wait<1>(); }
        else                { cp_wait<0>(); }
        __syncthreads();

        const uint32_t base = sb + (c & 1)*STAGE;
        #pragma unroll
        for (int ks = 0; ks < 4; ks++) {
            // B fragments (hi & lo), shared across convs
            uint32_t bh[4][2], bl[4][2];
            #pragma unroll
            for (int nt = 0; nt < 4; nt++) {
                int r = lane & 7, i = (lane >> 3) & 1;
                int nl = wn*32 + nt*8 + r;
                uint32_t seg = (uint32_t)(ks*2 + i);
                uint32_t ad = base + nl*128 + (((seg ^ (nl & 7)) & 7) << 4);
                ldsm_x2(bh[nt], ad);
                ldsm_x2(bl[nt], ad + 16384);
            }
            #pragma unroll
            for (int cv = 0; cv < NCONV; cv++) {
                uint32_t abase = base + (2 + 2*cv)*16384;
                uint32_t ah[3][4], al[3][4];
                #pragma unroll
                for (int mt = 0; mt < 3; mt++) {
                    int i = lane >> 3, r = lane & 7;
                    int ml = wm*48 + mt*16 + (i & 1)*8 + r;
                    uint32_t seg = (uint32_t)(ks*2 + (i >> 1));
                    uint32_t ad = abase + ml*128 + (((seg ^ (ml & 7)) & 7) << 4);
                    ldsm_x4(ah[mt], ad);
                    ldsm_x4(al[mt], ad + 16384);
                }
                #pragma unroll
                for (int mt = 0; mt < 3; mt++)
                    #pragma unroll
                    for (int nt = 0; nt < 4; nt++) {
                        mma_bf16(acc[cv][mt][nt], ah[mt], bh[nt]);
                        mma_bf16(acc[cv][mt][nt], ah[mt], bl[nt]);
                        mma_bf16(acc[cv][mt][nt], al[mt], bh[nt]);
                    }
            }
        }
        __syncthreads();
    }

    // ---- epilogue ----
    #pragma unroll
    for (int cv = 0; cv < NCONV; cv++) {
        float* dst = cv ? out1 : out0;
        #pragma unroll
        for (int mt = 0; mt < 3; mt++) {
            #pragma unroll
            for (int nt = 0; nt < 4; nt++) {
                int co0 = wm*48 + mt*16 + (lane >> 2);
                int p0  = ntile*NTILE + wn*32 + nt*8 + (lane & 3)*2;
                #pragma unroll
                for (int half = 0; half < 2; half++) {
                    int co = co0 + half*8;
                    float v0 = acc[cv][mt][nt][half*2 + 0];
                    float v1 = acc[cv][mt][nt][half*2 + 1];
                    if (EPI == 0) {
                        size_t obase = ((size_t)b*CH + co)*9*1024;
                        int h0 = p0 / IMG, w0 = p0 - h0*IMG;
                        int kk0 = (h0 % 3)*3 + (w0 % 3);
                        int l0  = (h0 / 3)*32 + (w0 / 3);
                        dst[obase + (size_t)kk0*1024 + l0] = v0;
                        int p1 = p0 + 1;
                        int h1 = p1 / IMG, w1 = p1 - h1*IMG;
                        int kk1 = (h1 % 3)*3 + (w1 % 3);
                        int l1  = (h1 / 3)*32 + (w1 / 3);
                        dst[obase + (size_t)kk1*1024 + l1] = v1;
                    } else {
                        size_t o = ((size_t)b*CH + co)*NPIX + p0;
                        dst[o]     = v0;
                        dst[o + 1] = v1;
                    }
                }
            }
        }
    }
}

// ---------------------------------------------------------------------------
// attn[b,k,c,d] = sum_l u1[b,c,k,l]*u2[b,d,k,l] -> S[b][d][c*9+k]  (fp32)
// ---------------------------------------------------------------------------
__global__ __launch_bounds__(256)
void attn_gemm_kernel(const float* __restrict__ u1, const float* __restrict__ u2,
                      float* __restrict__ S)
{
    __shared__ float sA[16][97];
    __shared__ float sB[16][97];
    const int bk = blockIdx.x;
    const int b = bk / 9;
    const int k = bk - 9*b;
    const float* A  = u1 + ((size_t)b*CH*9 + k)*1024;
    const float* Bm = u2 + ((size_t)b*CH*9 + k)*1024;
    const int tid = threadIdx.x;
    const int tx = tid & 15, ty = tid >> 4;

    float acc[6][6] = {};
    const int kk = tid & 15;
    const int cb = tid >> 4;
    for (int l0 = 0; l0 < 1024; l0 += 16) {
        #pragma unroll
        for (int it = 0; it < 6; it++) {
            int c = cb + it*16;
            sA[kk][c] = A [(size_t)c*9216 + l0 + kk];
            sB[kk][c] = Bm[(size_t)c*9216 + l0 + kk];
        }
        __syncthreads();
        #pragma unroll
        for (int q = 0; q < 16; q++) {
            float av[6], bv[6];
            #pragma unroll
            for (int i = 0; i < 6; i++) av[i] = sA[q][ty*6+i];
            #pragma unroll
            for (int j = 0; j < 6; j++) bv[j] = sB[q][tx*6+j];
            #pragma unroll
            for (int i = 0; i < 6; i++)
                #pragma unroll
                for (int j = 0; j < 6; j++)
                    acc[i][j] += av[i]*bv[j];
        }
        __syncthreads();
    }
    #pragma unroll
    for (int i = 0; i < 6; i++) {
        int c = ty*6 + i;
        #pragma unroll
        for (int j = 0; j < 6; j++) {
            int d = tx*6 + j;
            S[(((size_t)b*CH + d)*CH + c)*9 + k] = acc[i][j];
        }
    }
}

// ---------------------------------------------------------------------------
// softmax over 864 -> bf16 hi/lo padded rows [b][128][896]
// ---------------------------------------------------------------------------
__global__ __launch_bounds__(256)
void softmax_kernel(const float* __restrict__ S,
                    __nv_bfloat16* __restrict__ Sh, __nv_bfloat16* __restrict__ Sl)
{
    const int r = blockIdx.x;
    const int b = r / CH, d = r - b*CH;
    const float* row = S + (size_t)r * KREAL;
    const int tid = threadIdx.x;
    const float scale = 1.0f / 29.393876913398138f;   // 1/sqrt(864)

    float vals[4];
    int cnt = 0;
    float m = -1e30f;
    for (int i = tid; i < KREAL; i += 256) {
        float v = row[i] * scale;
        vals[cnt++] = v;
        m = fmaxf(m, v);
    }
    __shared__ float redm[8], reds[8];
    #pragma unroll
    for (int o = 16; o; o >>= 1) m = fmaxf(m, __shfl_xor_sync(0xffffffffu, m, o));
    if ((tid & 31) == 0) redm[tid >> 5] = m;
    __syncthreads();
    float bm = redm[0];
    #pragma unroll
    for (int w = 1; w < 8; w++) bm = fmaxf(bm, redm[w]);

    float s = 0.f;
    for (int c = 0; c < cnt; c++) { vals[c] = expf(vals[c] - bm); s += vals[c]; }
    #pragma unroll
    for (int o = 16; o; o >>= 1) s += __shfl_xor_sync(0xffffffffu, s, o);
    if ((tid & 31) == 0) reds[tid >> 5] = s;
    __syncthreads();
    float bs = 0.f;
    #pragma unroll
    for (int w = 0; w < 8; w++) bs += reds[w];
    float inv = 1.0f / bs;

    size_t obase = ((size_t)b*128 + d) * KPAD;
    cnt = 0;
    for (int i = tid; i < KREAL; i += 256) {
        float v = vals[cnt++] * inv;
        __nv_bfloat16 hi = __float2bfloat16(v);
        __nv_bfloat16 lo = __float2bfloat16(v - __bfloat162float(hi));
        Sh[obase + i] = hi; Sl[obase + i] = lo;
    }
}

// ---------------------------------------------------------------------------
extern "C" void kernel_launch(void* const* d_in, const int* in_sizes, int n_in,
                              void* d_out, int out_size)
{
    const float* x  = (const float*)d_in[0];
    const float* W1 = (const float*)d_in[1];
    const float* W2 = (const float*)d_in[2];
    const float* W3 = (const float*)d_in[3];
    float* out = (float*)d_out;

    __nv_bfloat16 *Bhi, *Blo, *W12h, *W12l, *W3h, *W3l, *Sh, *Sl;
    float *u1, *u2, *y3, *S;
    cudaGetSymbolAddress((void**)&Bhi, g_Bhi);   cudaGetSymbolAddress((void**)&Blo, g_Blo);
    cudaGetSymbolAddress((void**)&W12h, g_W12h); cudaGetSymbolAddress((void**)&W12l, g_W12l);
    cudaGetSymbolAddress((void**)&W3h, g_W3h);   cudaGetSymbolAddress((void**)&W3l, g_W3l);
    cudaGetSymbolAddress((void**)&Sh, g_Sh);     cudaGetSymbolAddress((void**)&Sl, g_Sl);
    cudaGetSymbolAddress((void**)&u1, g_u1);     cudaGetSymbolAddress((void**)&u2, g_u2);
    cudaGetSymbolAddress((void**)&y3, g_y3);     cudaGetSymbolAddress((void**)&S,  g_S);

    const int smem2 = 2*6*16384;   // 196608  (NCONV=2, double-buffered)
    const int smem1 = 2*4*16384;   // 131072  (NCONV=1)
    cudaFuncSetAttribute(gemm_conv_kernel<2,0>, cudaFuncAttributeMaxDynamicSharedMemorySize, smem2);
    cudaFuncSetAttribute(gemm_conv_kernel<1,1>, cudaFuncAttributeMaxDynamicSharedMemorySize, smem1);

    prep_w_kernel<<<(3*CH*KREAL + 255)/256, 256>>>(W1, W2, W3);
    prep_shift_kernel<<<dim3(IMG, 3, NB), 256>>>(x, Bhi, Blo);

    dim3 gg(TILES_PER_B, NB);
    // conv1 + conv2 (shared B) -> unfold layouts u1, u2
    gemm_conv_kernel<2,0><<<gg, 256, smem2>>>(Bhi, Blo, W12h, W12l,
                                              W12h + (size_t)128*KPAD, W12l + (size_t)128*KPAD,
                                              0, u1, u2);
    // conv3 -> y3 NCHW
    gemm_conv_kernel<1,1><<<gg, 256, smem1>>>(Bhi, Blo, W3h, W3l, nullptr, nullptr, 0, y3, nullptr);

    attn_gemm_kernel<<<NB*9, 256>>>(u1, u2, S);
    softmax_kernel<<<NB*CH, 256>>>(S, Sh, Sl);

    // y3 -> shifted Ys hi/lo (reuse B buffers)
    prep_shift_kernel<<<dim3(IMG, 3, NB), 256>>>(y3, Bhi, Blo);
    // conv4: per-batch A = softmaxed attention
    gemm_conv_kernel<1,1><<<gg, 256, smem1>>>(Bhi, Blo, Sh, Sl, nullptr, nullptr,
                                              (long)128*KPAD, out, nullptr);
}

// round 7
// speedup vs baseline: 2.5526x; 1.4846x over previous
#include <cuda_runtime.h>
#include <cuda_bf16.h>
#include <cstdint>

#define IMG 96
#define CH 96
#define NB 16
#define NPIX (IMG*IMG)           // 9216
#define PPIX (98*98)             // 9604 padded pixels (1-halo)
#define KTOT 864                 // 9 taps * 96 ci, = 27*32 exactly
#define NCHUNK 27                // K chunks of 32
#define NTILE 128                // pixels per GEMM tile
#define TILES_PER_B 72
#define ROWB 80                  // smem row stride bytes (64B data + 16B pad; x5 spread = conflict-free)

typedef __nv_bfloat16 bf16;

// ---------------- device scratch (BSS => zero; halo rows never written => stay 0) ----
__device__ __align__(128) bf16 g_xTh[(size_t)NB*PPIX*CH];   // transposed padded input hi (x, later y3)
__device__ __align__(128) bf16 g_xTl[(size_t)NB*PPIX*CH];   // lo
__device__ __align__(128) bf16 g_Wh[(size_t)3*CH*KTOT];     // weights, K order tap*96+ci
__device__ __align__(128) bf16 g_Wl[(size_t)3*CH*KTOT];
__device__ __align__(128) bf16 g_Snh[(size_t)NB*CH*KTOT];   // softmaxed attn weights hi
__device__ __align__(128) bf16 g_Snl[(size_t)NB*CH*KTOT];
__device__ float g_u1[(size_t)NB*CH*9*1024];   // unfolded conv1 out
__device__ float g_u2[(size_t)NB*CH*9*1024];   // unfolded conv2 out
__device__ float g_y3[(size_t)NB*CH*NPIX];     // conv3 out NCHW
__device__ float g_P [(size_t)NB*9*4*CH*CH];   // attn split-L partials
__device__ float g_S [(size_t)NB*CH*KTOT];     // attn logits

// ---------------- helpers ----------------
__device__ __forceinline__ uint32_t smem_u32(const void* p) {
    uint32_t a;
    asm("{ .reg .u64 t; cvta.to.shared.u64 t, %1; cvt.u32.u64 %0, t; }" : "=r"(a) : "l"(p));
    return a;
}
__device__ __forceinline__ void cp_async16(uint32_t dst, const void* src) {
    asm volatile("cp.async.cg.shared.global [%0], [%1], 16;" :: "r"(dst), "l"(src));
}
__device__ __forceinline__ void cp_commit() { asm volatile("cp.async.commit_group;" ::: "memory"); }
template<int N>
__device__ __forceinline__ void cp_wait() { asm volatile("cp.async.wait_group %0;" :: "n"(N) : "memory"); }

__device__ __forceinline__ void ldsm_x4(uint32_t* r, uint32_t addr) {
    asm volatile("ldmatrix.sync.aligned.m8n8.x4.shared.b16 {%0,%1,%2,%3}, [%4];"
                 : "=r"(r[0]), "=r"(r[1]), "=r"(r[2]), "=r"(r[3]) : "r"(addr));
}
__device__ __forceinline__ void ldsm_x2(uint32_t* r, uint32_t addr) {
    asm volatile("ldmatrix.sync.aligned.m8n8.x2.shared.b16 {%0,%1}, [%2];"
                 : "=r"(r[0]), "=r"(r[1]) : "r"(addr));
}
__device__ __forceinline__ void mma_bf16(float* d, const uint32_t* a, const uint32_t* b) {
    asm volatile("mma.sync.aligned.m16n8k16.row.col.f32.bf16.bf16.f32 "
                 "{%0,%1,%2,%3}, {%4,%5,%6,%7}, {%8,%9}, {%0,%1,%2,%3};"
                 : "+f"(d[0]), "+f"(d[1]), "+f"(d[2]), "+f"(d[3])
                 : "r"(a[0]), "r"(a[1]), "r"(a[2]), "r"(a[3]), "r"(b[0]), "r"(b[1]));
}
__device__ __forceinline__ uint32_t pack2(bf16 a, bf16 b) {
    __nv_bfloat162 t(a, b);
    return *reinterpret_cast<uint32_t*>(&t);
}

// ---------------------------------------------------------------------------
// prepT: src NCHW fp32 -> transposed padded [b][(h+1)*98+(w+1)][ci] bf16 hi/lo.
// grid (96 h, 16 b), 256 thr
// ---------------------------------------------------------------------------
__global__ __launch_bounds__(256)
void prepT_kernel(const float* __restrict__ src,
                  bf16* __restrict__ dhi, bf16* __restrict__ dlo)
{
    __shared__ float s[CH][97];
    const int h = blockIdx.x, b = blockIdx.y, tid = threadIdx.x;

    for (int e = tid; e < CH*IMG; e += 256) {
        int ci = e / IMG, w = e - ci*IMG;
        s[ci][w] = src[(((size_t)b*CH + ci)*IMG + h)*IMG + w];
    }
    __syncthreads();

    for (int e = tid; e < IMG*12; e += 256) {       // 12 x 16B segs of 8 ci each
        int w = e / 12, seg = e - w*12;
        int ci0 = seg*8;
        uint32_t uh[4], ul[4];
        #pragma unroll
        for (int i2 = 0; i2 < 4; i2++) {
            float a = s[ci0 + i2*2][w], c2 = s[ci0 + i2*2 + 1][w];
            bf16 ha = __float2bfloat16(a), hc = __float2bfloat16(c2);
            bf16 la = __float2bfloat16(a - __bfloat162float(ha));
            bf16 lc = __float2bfloat16(c2 - __bfloat162float(hc));
            uh[i2] = pack2(ha, hc);
            ul[i2] = pack2(la, lc);
        }
        size_t base = ((size_t)b*PPIX + (size_t)(h+1)*98 + (w+1))*CH + ci0;
        *reinterpret_cast<uint4*>(dhi + base) = make_uint4(uh[0],uh[1],uh[2],uh[3]);
        *reinterpret_cast<uint4*>(dlo + base) = make_uint4(ul[0],ul[1],ul[2],ul[3]);
    }
}

// ---------------------------------------------------------------------------
// prep_w: W[co][ci][3][3] fp32 -> g_W{h,l}[conv][co][tap*96+ci]
// ---------------------------------------------------------------------------
__global__ __launch_bounds__(256)
void prep_w_kernel(const float* __restrict__ W1, const float* __restrict__ W2,
                   const float* __restrict__ W3)
{
    int idx = blockIdx.x*256 + threadIdx.x;
    if (idx >= 3*CH*KTOT) return;
    int conv = idx / (CH*KTOT);
    int r = idx - conv*(CH*KTOT);
    int co = r / KTOT, k = r - co*KTOT;
    int tap = k / CH, ci = k - tap*CH;
    const float* W = (conv == 0) ? W1 : (conv == 1) ? W2 : W3;
    float v = W[((size_t)co*CH + ci)*9 + tap];
    bf16 hi = __float2bfloat16(v);
    g_Wh[idx] = hi;
    g_Wl[idx] = __float2bfloat16(v - __bfloat162float(hi));
}

// ---------------------------------------------------------------------------
// gemm_conv2: D[co][p] = sum_k A[co][k]*B[p][k], hi/lo 3-term bf16 mma.
// B gathered on the fly from transposed-padded input: chunk (tap, ci0) rows are
// xT rows at pixel + (dh*98+dw). M=96, N=128/tile, K=864 = 27 chunks of 32.
// MODE 0 (NCONV=3): cv0,cv1 -> unfold layout (u1,u2); cv2 -> NCHW (y3).
// MODE 1 (NCONV=1): NCHW -> o0 (per-batch A via aStride).
// ---------------------------------------------------------------------------
template<int NCONV, int MODE>
__global__ __launch_bounds__(256, 1)
void gemm_conv2(const bf16* __restrict__ Bh_, const bf16* __restrict__ Bl_,
                const bf16* __restrict__ Ah_, const bf16* __restrict__ Al_,
                long aStride, float* __restrict__ o0, float* __restrict__ o1,
                float* __restrict__ o2)
{
    extern __shared__ __align__(1024) char smem[];
    constexpr int AOFF  = 2*NTILE*ROWB;          // 20480: after Bh,Bl
    constexpr int ABUF  = 96*ROWB;               // 7680
    constexpr int STAGE = AOFF + NCONV*2*ABUF;

    const int tid = threadIdx.x, wid = tid >> 5, lane = tid & 31;
    const int wm = wid & 1, wn = wid >> 1;
    const int ntile = blockIdx.x, b = blockIdx.y;
    const uint32_t sb = smem_u32(smem);

    // per-thread load slots: (row, seg) with row = tid>>2 and row+64
    const int r0 = tid >> 2, seg0 = tid & 3;
    const int q0 = ntile*NTILE + r0;
    const int pb0 = (q0/IMG)*98 + (q0 - (q0/IMG)*IMG);
    const int q1 = q0 + 64;
    const int pb1 = (q1/IMG)*98 + (q1 - (q1/IMG)*IMG);

    const bf16* Bs[2] = { Bh_ + (size_t)b*PPIX*CH, Bl_ + (size_t)b*PPIX*CH };
    const bf16* As[2] = { Ah_ + (size_t)b*aStride, Al_ + (size_t)b*aStride };

    float acc[NCONV][3][4][4];
    #pragma unroll
    for (int cv = 0; cv < NCONV; cv++)
        #pragma unroll
        for (int mt = 0; mt < 3; mt++)
            #pragma unroll
            for (int nt = 0; nt < 4; nt++)
                #pragma unroll
                for (int j = 0; j < 4; j++) acc[cv][mt][nt][j] = 0.f;

    auto load_chunk = [&](int chunk, int stage) {
        const int tap = chunk/3;
        const int ci0 = (chunk - tap*3)*32;
        const int dh = tap/3, dw = tap - dh*3;
        const int doff = dh*98 + dw;
        const int koff = tap*CH + ci0;
        const uint32_t base = sb + stage*STAGE;
        #pragma unroll
        for (int t = 0; t < 2; t++) {
            cp_async16(base + t*(NTILE*ROWB) + r0*ROWB + seg0*16,
                       Bs[t] + (size_t)(pb0 + doff)*CH + ci0 + seg0*8);
            cp_async16(base + t*(NTILE*ROWB) + (r0+64)*ROWB + seg0*16,
                       Bs[t] + (size_t)(pb1 + doff)*CH + ci0 + seg0*8);
        }
        #pragma unroll
        for (int t = 0; t < NCONV; t++) {
            #pragma unroll
            for (int hl = 0; hl < 2; hl++) {
                const bf16* src = As[hl] + (size_t)t*CH*KTOT + koff;
                uint32_t abase = base + AOFF + (t*2 + hl)*ABUF;
                cp_async16(abase + r0*ROWB + seg0*16, src + (size_t)r0*KTOT + seg0*8);
                if (tid < 128)
                    cp_async16(abase + (r0+64)*ROWB + seg0*16,
                               src + (size_t)(r0+64)*KTOT + seg0*8);
            }
        }
        cp_commit();
    };

    load_chunk(0, 0);

    for (int c = 0; c < NCHUNK; c++) {
        if (c + 1 < NCHUNK) { load_chunk(c+1, (c+1)&1); cp_wait<1>(); }
        else                { cp_wait<0>(); }
        __syncthreads();

        const uint32_t base = sb + (c & 1)*STAGE;
        #pragma unroll
        for (int ks = 0; ks < 2; ks++) {
            uint32_t bh[4][2], bl[4][2];
            #pragma unroll
            for (int nt = 0; nt < 4; nt++) {
                int rr = lane & 7, ii = (lane >> 3) & 1;
                int nl = wn*32 + nt*8 + rr;
                uint32_t ad = base + nl*ROWB + (ks*2 + ii)*16;
                ldsm_x2(bh[nt], ad);
                ldsm_x2(bl[nt], ad + NTILE*ROWB);
            }
            #pragma unroll
            for (int cv = 0; cv < NCONV; cv++) {
                uint32_t ab = base + AOFF + cv*2*ABUF;
                uint32_t ah[3][4], al[3][4];
                #pragma unroll
                for (int mt = 0; mt < 3; mt++) {
                    int ii = lane >> 3, rr = lane & 7;
                    int ml = wm*48 + mt*16 + (ii & 1)*8 + rr;
                    uint32_t ad = ab + ml*ROWB + (ks*2 + (ii >> 1))*16;
                    ldsm_x4(ah[mt], ad);
                    ldsm_x4(al[mt], ad + ABUF);
                }
                #pragma unroll
                for (int mt = 0; mt < 3; mt++)
                    #pragma unroll
                    for (int nt = 0; nt < 4; nt++) {
                        mma_bf16(acc[cv][mt][nt], ah[mt], bh[nt]);
                        mma_bf16(acc[cv][mt][nt], ah[mt], bl[nt]);
                        mma_bf16(acc[cv][mt][nt], al[mt], bh[nt]);
                    }
            }
        }
        __syncthreads();
    }

    // ---- epilogue ----
    #pragma unroll
    for (int cv = 0; cv < NCONV; cv++) {
        float* dst = (MODE == 1) ? o0 : (cv == 0 ? o0 : (cv == 1 ? o1 : o2));
        const bool unfold = (MODE == 0 && cv < 2);
        #pragma unroll
        for (int mt = 0; mt < 3; mt++) {
            #pragma unroll
            for (int nt = 0; nt < 4; nt++) {
                int co0 = wm*48 + mt*16 + (lane >> 2);
                int p0  = ntile*NTILE + wn*32 + nt*8 + (lane & 3)*2;
                #pragma unroll
                for (int half = 0; half < 2; half++) {
                    int co = co0 + half*8;
                    float v0 = acc[cv][mt][nt][half*2 + 0];
                    float v1 = acc[cv][mt][nt][half*2 + 1];
                    if (unfold) {
                        size_t obase = ((size_t)b*CH + co)*9*1024;
                        int h0 = p0 / IMG, w0 = p0 - h0*IMG;
                        dst[obase + (size_t)((h0%3)*3 + (w0%3))*1024 + (h0/3)*32 + (w0/3)] = v0;
                        int p1 = p0 + 1;
                        int h1 = p1 / IMG, w1 = p1 - h1*IMG;
                        dst[obase + (size_t)((h1%3)*3 + (w1%3))*1024 + (h1/3)*32 + (w1/3)] = v1;
                    } else {
                        size_t o = ((size_t)b*CH + co)*NPIX + p0;
                        dst[o]     = v0;
                        dst[o + 1] = v1;
                    }
                }
            }
        }
    }
}

// ---------------------------------------------------------------------------
// attn partials: P[(bk*4+s)][c][d] = sum_{l in s-th 256} u1[b,c,k,l]*u2[b,d,k,l]
// ---------------------------------------------------------------------------
__global__ __launch_bounds__(256)
void attn_partial_kernel(const float* __restrict__ u1, const float* __restrict__ u2,
                         float* __restrict__ P)
{
    __shared__ float sA[16][97];
    __shared__ float sB[16][97];
    const int g = blockIdx.x;
    const int s = g & 3, bk = g >> 2;
    const int b = bk / 9, k = bk - 9*b;
    const float* A  = u1 + ((size_t)b*CH*9 + k)*1024 + s*256;
    const float* Bm = u2 + ((size_t)b*CH*9 + k)*1024 + s*256;
    const int tid = threadIdx.x;
    const int tx = tid & 15, ty = tid >> 4;

    float acc[6][6] = {};
    const int kk = tid & 15;
    const int cb = tid >> 4;
    for (int l0 = 0; l0 < 256; l0 += 16) {
        #pragma unroll
        for (int it = 0; it < 6; it++) {
            int c = cb + it*16;
            sA[kk][c] = A [(size_t)c*9216 + l0 + kk];
            sB[kk][c] = Bm[(size_t)c*9216 + l0 + kk];
        }
        __syncthreads();
        #pragma unroll
        for (int q = 0; q < 16; q++) {
            float av[6], bv[6];
            #pragma unroll
            for (int i = 0; i < 6; i++) av[i] = sA[q][ty*6+i];
            #pragma unroll
            for (int j = 0; j < 6; j++) bv[j] = sB[q][tx*6+j];
            #pragma unroll
            for (int i = 0; i < 6; i++)
                #pragma unroll
                for (int j = 0; j < 6; j++)
                    acc[i][j] += av[i]*bv[j];
        }
        __syncthreads();
    }
    size_t pbase = (size_t)(bk*4 + s)*CH*CH;
    #pragma unroll
    for (int i = 0; i < 6; i++) {
        int c = ty*6 + i;
        #pragma unroll
        for (int j = 0; j < 6; j++)
            P[pbase + (size_t)c*CH + tx*6 + j] = acc[i][j];
    }
}

// ---------------------------------------------------------------------------
// reduce 4 partials -> S[((b*96+d)*96+c)*9+k]  (softmax row layout)
// ---------------------------------------------------------------------------
__global__ __launch_bounds__(256)
void attn_reduce_kernel(const float* __restrict__ P, float* __restrict__ S)
{
    int e = blockIdx.x*256 + threadIdx.x;
    if (e >= NB*CH*CH*9) return;
    int k = e % 9;
    int c = (e / 9) % CH;
    int d = (e / 864) % CH;
    int b = e / (864*CH);
    size_t base = (size_t)(b*9 + k)*4*CH*CH + (size_t)c*CH + d;
    S[e] = P[base] + P[base + CH*CH] + P[base + 2*CH*CH] + P[base + 3*CH*CH];
}

// ---------------------------------------------------------------------------
// softmax over 864 -> Sn hi/lo with K order tap*96+c
// ---------------------------------------------------------------------------
__global__ __launch_bounds__(256)
void softmax_kernel(const float* __restrict__ S,
                    bf16* __restrict__ Sh, bf16* __restrict__ Sl)
{
    const int r = blockIdx.x;
    const int b = r / CH, d = r - b*CH;
    const float* row = S + (size_t)r * KTOT;
    const int tid = threadIdx.x;
    const float scale = 1.0f / 29.393876913398138f;   // 1/sqrt(864)

    float vals[4];
    int cnt = 0;
    float m = -1e30f;
    for (int i = tid; i < KTOT; i += 256) {
        float v = row[i] * scale;
        vals[cnt++] = v;
        m = fmaxf(m, v);
    }
    __shared__ float redm[8], reds[8];
    #pragma unroll
    for (int o = 16; o; o >>= 1) m = fmaxf(m, __shfl_xor_sync(0xffffffffu, m, o));
    if ((tid & 31) == 0) redm[tid >> 5] = m;
    __syncthreads();
    float bm = redm[0];
    #pragma unroll
    for (int w = 1; w < 8; w++) bm = fmaxf(bm, redm[w]);

    float s = 0.f;
    for (int c = 0; c < cnt; c++) { vals[c] = expf(vals[c] - bm); s += vals[c]; }
    #pragma unroll
    for (int o = 16; o; o >>= 1) s += __shfl_xor_sync(0xffffffffu, s, o);
    if ((tid & 31) == 0) reds[tid >> 5] = s;
    __syncthreads();
    float bs = 0.f;
    #pragma unroll
    for (int w = 0; w < 8; w++) bs += reds[w];
    float inv = 1.0f / bs;

    size_t obase = ((size_t)b*CH + d) * KTOT;
    cnt = 0;
    for (int i = tid; i < KTOT; i += 256) {
        float v = vals[cnt++] * inv;
        int c = i / 9, tap = i - c*9;
        bf16 hi = __float2bfloat16(v);
        size_t o = obase + tap*CH + c;
        Sh[o] = hi;
        Sl[o] = __float2bfloat16(v - __bfloat162float(hi));
    }
}

// ---------------------------------------------------------------------------
extern "C" void kernel_launch(void* const* d_in, const int* in_sizes, int n_in,
                              void* d_out, int out_size)
{
    const float* x  = (const float*)d_in[0];
    const float* W1 = (const float*)d_in[1];
    const float* W2 = (const float*)d_in[2];
    const float* W3 = (const float*)d_in[3];
    float* out = (float*)d_out;

    bf16 *xTh, *xTl, *Wh, *Wl, *Snh, *Snl;
    float *u1, *u2, *y3, *P, *S;
    cudaGetSymbolAddress((void**)&xTh, g_xTh); cudaGetSymbolAddress((void**)&xTl, g_xTl);
    cudaGetSymbolAddress((void**)&Wh,  g_Wh);  cudaGetSymbolAddress((void**)&Wl,  g_Wl);
    cudaGetSymbolAddress((void**)&Snh, g_Snh); cudaGetSymbolAddress((void**)&Snl, g_Snl);
    cudaGetSymbolAddress((void**)&u1,  g_u1);  cudaGetSymbolAddress((void**)&u2,  g_u2);
    cudaGetSymbolAddress((void**)&y3,  g_y3);  cudaGetSymbolAddress((void**)&P,   g_P);
    cudaGetSymbolAddress((void**)&S,   g_S);

    const int smem3 = 2*(2*NTILE*ROWB + 6*96*ROWB);   // 133120
    const int smem1 = 2*(2*NTILE*ROWB + 2*96*ROWB);   // 71680
    cudaFuncSetAttribute(gemm_conv2<3,0>, cudaFuncAttributeMaxDynamicSharedMemorySize, smem3);
    cudaFuncSetAttribute(gemm_conv2<1,1>, cudaFuncAttributeMaxDynamicSharedMemorySize, smem1);

    prep_w_kernel<<<(3*CH*KTOT + 255)/256, 256>>>(W1, W2, W3);
    prepT_kernel<<<dim3(IMG, NB), 256>>>(x, xTh, xTl);

    dim3 gg(TILES_PER_B, NB);
    // fused conv1+conv2+conv3 (B loaded once)
    gemm_conv2<3,0><<<gg, 256, smem3>>>(xTh, xTl, Wh, Wl, 0, u1, u2, y3);

    attn_partial_kernel<<<NB*9*4, 256>>>(u1, u2, P);
    attn_reduce_kernel<<<(NB*CH*CH*9 + 255)/256, 256>>>(P, S);
    softmax_kernel<<<NB*CH, 256>>>(S, Snh, Snl);

    // y3 -> transposed padded (reuse xT buffers)
    prepT_kernel<<<dim3(IMG, NB), 256>>>(y3, xTh, xTl);
    // conv4: per-batch A = softmaxed attention
    gemm_conv2<1,1><<<gg, 256, smem1>>>(xTh, xTl, Snh, Snl, (long)CH*KTOT,
                                        out, nullptr, nullptr);
}